// round 14
// baseline (speedup 1.0000x reference)
#include <cuda_runtime.h>
#include <cuda_bf16.h>
#include <cstdint>

// Problem constants
#define NH   8
#define DK   32
#define TLEN 2048
#define NB   4
#define DM   256
#define ROWS (NB * TLEN)   // 8192

// ---------------- device scratch (allocation-free rule) ----------------
__device__ uint32_t g_qh[ROWS * 128], g_ql[ROWS * 128];
__device__ uint32_t g_kh[ROWS * 128], g_kl[ROWS * 128];
__device__ uint32_t g_vh[ROWS * 128], g_vl[ROWS * 128];
__device__ float    g_O [ROWS * DM];
// transposed split weights: [4 W][256 n][128 kpair]
__device__ uint32_t g_wth[4 * 256 * 128], g_wtl[4 * 256 * 128];
// pre-transposed V: [n][h][32 dv][1024 keypair u32]
__device__ uint32_t g_vth[NB * NH * 32 * 1024], g_vtl[NB * NH * 32 * 1024];

// ---------------- helpers ----------------
__device__ __forceinline__ float fast_exp2(float x) {
    float y;
    asm("ex2.approx.f32 %0, %1;" : "=f"(y) : "f"(x));
    return y;
}
__device__ __forceinline__ uint32_t packbf2(float x0, float x1) {
    uint32_t d;
    asm("cvt.rn.bf16x2.f32 %0, %1, %2;" : "=r"(d) : "f"(x1), "f"(x0));
    return d;
}
__device__ __forceinline__ void split2(float x0, float x1, uint32_t& h, uint32_t& l) {
    h = packbf2(x0, x1);
    float h0 = __uint_as_float(h << 16);
    float h1 = __uint_as_float(h & 0xFFFF0000u);
    l = packbf2(x0 - h0, x1 - h1);
}
__device__ __forceinline__ void mma_bf16(float* c, const uint32_t* a,
                                         uint32_t b0, uint32_t b1) {
    asm volatile(
        "mma.sync.aligned.m16n8k16.row.col.f32.bf16.bf16.f32 "
        "{%0,%1,%2,%3}, {%4,%5,%6,%7}, {%8,%9}, {%0,%1,%2,%3};"
        : "+f"(c[0]), "+f"(c[1]), "+f"(c[2]), "+f"(c[3])
        : "r"(a[0]), "r"(a[1]), "r"(a[2]), "r"(a[3]), "r"(b0), "r"(b1));
}
__device__ __forceinline__ void mma_bf16r(float* c, uint32_t a0, uint32_t a1,
                                          uint32_t a2, uint32_t a3,
                                          uint32_t b0, uint32_t b1) {
    asm volatile(
        "mma.sync.aligned.m16n8k16.row.col.f32.bf16.bf16.f32 "
        "{%0,%1,%2,%3}, {%4,%5,%6,%7}, {%8,%9}, {%0,%1,%2,%3};"
        : "+f"(c[0]), "+f"(c[1]), "+f"(c[2]), "+f"(c[3])
        : "r"(a0), "r"(a1), "r"(a2), "r"(a3), "r"(b0), "r"(b1));
}
__device__ __forceinline__ void ldsm4(uint32_t addr, uint32_t& r0, uint32_t& r1,
                                      uint32_t& r2, uint32_t& r3) {
    asm volatile("ldmatrix.sync.aligned.m8n8.x4.shared.b16 {%0,%1,%2,%3}, [%4];"
                 : "=r"(r0), "=r"(r1), "=r"(r2), "=r"(r3) : "r"(addr));
}
__device__ __forceinline__ uint32_t smem_u32(const void* p) {
    uint32_t a;
    asm("{ .reg .u64 t; cvta.to.shared.u64 t, %1; cvt.u32.u64 %0, t; }" : "=r"(a) : "l"(p));
    return a;
}
__device__ __forceinline__ void cp16(uint32_t daddr, const void* g) {
    asm volatile("cp.async.ca.shared.global [%0], [%1], 16;"
                 :: "r"(daddr), "l"(g) : "memory");
}
#define CP_COMMIT asm volatile("cp.async.commit_group;" ::: "memory")
#define CP_WAIT0  asm volatile("cp.async.wait_group 0;" ::: "memory")
#define CP_WAIT1  asm volatile("cp.async.wait_group 1;" ::: "memory")

// ---------------- prep: W -> transposed split bf16 pairs (Wq pre-scaled) ----------------
__global__ __launch_bounds__(256) void prep_w(const float* __restrict__ W0,
                                              const float* __restrict__ W1,
                                              const float* __restrict__ W2,
                                              const float* __restrict__ W3) {
    const int idx = blockIdx.x * 256 + threadIdx.x;
    const int w = idx >> 15;
    const int r = idx & 32767;
    const int n = r >> 7, kp = r & 127;
    const float* W = (w == 0) ? W0 : (w == 1) ? W1 : (w == 2) ? W2 : W3;
    const float sc = (w == 0) ? 0.25503480f : 1.0f;   // log2(e)/sqrt(32) folded into Wq
    float x0 = W[(size_t)(2 * kp) * 256 + n] * sc;
    float x1 = W[(size_t)(2 * kp + 1) * 256 + n] * sc;
    uint32_t h, l;
    split2(x0, x1, h, l);
    g_wth[idx] = h;
    g_wtl[idx] = l;
}

// ---------------- software-pipelined HMMA GEMM: C = A @ W (unchanged) ----------------
#define GS 20
#define GB_AL 10240
#define GB_BH 20480
#define GB_BL 25600
#define GBUF  30720
#define GEMM_SMEM (2 * GBUF)

__device__ __forceinline__ void gemm_body_pipe(const float* __restrict__ A,
                                               const uint32_t* __restrict__ Bth,
                                               const uint32_t* __restrict__ Btl,
                                               uint32_t* __restrict__ outh,
                                               uint32_t* __restrict__ outl,
                                               float* __restrict__ outf,
                                               char* gsm, int bm, int bn) {
    const int tid = threadIdx.x;
    const int lane = tid & 31;
    const int wid = tid >> 5;
    const int qr = lane >> 2;
    const int lm = lane & 3;
    const int m0w = wid * 16;

    const int br = tid >> 2;
    const int bc = (tid & 3) * 4;

    float4 pa[4];
    uint4 pbh, pbl;

    auto ldg = [&](int kc) {
#pragma unroll
        for (int t = 0; t < 4; t++) {
            int idx = tid + t * 256;
            int r = idx >> 3, c4 = idx & 7;
            pa[t] = *(const float4*)&A[(size_t)(bm + r) * 256 + kc * 32 + c4 * 4];
        }
        pbh = *(const uint4*)&Bth[(size_t)(bn + br) * 128 + kc * 16 + bc];
        pbl = *(const uint4*)&Btl[(size_t)(bn + br) * 128 + kc * 16 + bc];
    };
    auto sts = [&](int buf) {
        uint32_t* sAh = (uint32_t*)(gsm + buf * GBUF);
        uint32_t* sAl = (uint32_t*)(gsm + buf * GBUF + GB_AL);
        uint32_t* sBh = (uint32_t*)(gsm + buf * GBUF + GB_BH);
        uint32_t* sBl = (uint32_t*)(gsm + buf * GBUF + GB_BL);
#pragma unroll
        for (int t = 0; t < 4; t++) {
            int idx = tid + t * 256;
            int r = idx >> 3, c4 = idx & 7;
            uint32_t h0, l0, h1, l1;
            split2(pa[t].x, pa[t].y, h0, l0);
            split2(pa[t].z, pa[t].w, h1, l1);
            sAh[r * GS + c4 * 2]     = h0;
            sAh[r * GS + c4 * 2 + 1] = h1;
            sAl[r * GS + c4 * 2]     = l0;
            sAl[r * GS + c4 * 2 + 1] = l1;
        }
        *(uint4*)&sBh[br * GS + bc] = pbh;
        *(uint4*)&sBl[br * GS + bc] = pbl;
    };

    float C[8][4];
#pragma unroll
    for (int f = 0; f < 8; f++)
#pragma unroll
        for (int i = 0; i < 4; i++) C[f][i] = 0.0f;

    ldg(0);
    sts(0);
    __syncthreads();

    for (int kc = 0; kc < 8; kc++) {
        const int cur = kc & 1;
        if (kc + 1 < 8) ldg(kc + 1);

        const uint32_t* sAh = (const uint32_t*)(gsm + cur * GBUF);
        const uint32_t* sAl = (const uint32_t*)(gsm + cur * GBUF + GB_AL);
        const uint32_t* sBh = (const uint32_t*)(gsm + cur * GBUF + GB_BH);
        const uint32_t* sBl = (const uint32_t*)(gsm + cur * GBUF + GB_BL);

#pragma unroll
        for (int j = 0; j < 2; j++) {
            const int ab = (m0w + qr) * GS + j * 8 + lm;
            uint32_t ah0 = sAh[ab],     ah1 = sAh[ab + 8 * GS];
            uint32_t ah2 = sAh[ab + 4], ah3 = sAh[ab + 8 * GS + 4];
            uint32_t al0 = sAl[ab],     al1 = sAl[ab + 8 * GS];
            uint32_t al2 = sAl[ab + 4], al3 = sAl[ab + 8 * GS + 4];
#pragma unroll
            for (int f = 0; f < 8; f++) {
                const int bb = (f * 8 + qr) * GS + j * 8 + lm;
                uint32_t bh0 = sBh[bb], bh1 = sBh[bb + 4];
                uint32_t bl0 = sBl[bb], bl1 = sBl[bb + 4];
                mma_bf16r(C[f], ah0, ah1, ah2, ah3, bh0, bh1);
                mma_bf16r(C[f], ah0, ah1, ah2, ah3, bl0, bl1);
                mma_bf16r(C[f], al0, al1, al2, al3, bh0, bh1);
            }
        }
        if (kc + 1 < 8) sts(cur ^ 1);
        __syncthreads();
    }

    if (outh) {
#pragma unroll
        for (int f = 0; f < 8; f++) {
            uint32_t h, l;
            size_t o0 = (size_t)(bm + m0w + qr) * 128 + (bn >> 1) + f * 4 + lm;
            split2(C[f][0], C[f][1], h, l);
            outh[o0] = h; outl[o0] = l;
            split2(C[f][2], C[f][3], h, l);
            outh[o0 + 8 * 128] = h; outl[o0 + 8 * 128] = l;
        }
    } else {
#pragma unroll
        for (int f = 0; f < 8; f++) {
            size_t r0 = (size_t)(bm + m0w + qr) * 256 + bn + f * 8 + lm * 2;
            *(float2*)&outf[r0]           = make_float2(C[f][0], C[f][1]);
            *(float2*)&outf[r0 + 8 * 256] = make_float2(C[f][2], C[f][3]);
        }
    }
}

__global__ __launch_bounds__(256, 2) void gemm3(const float* __restrict__ query,
                                                const float* __restrict__ key) {
    extern __shared__ char gsm[];
    const int z = blockIdx.z;
    const float* A = (z == 2) ? key : query;
    const uint32_t* Bth = g_wth + (size_t)z * 32768;
    const uint32_t* Btl = g_wtl + (size_t)z * 32768;
    uint32_t* oh = (z == 0) ? g_qh : (z == 1) ? g_kh : g_vh;
    uint32_t* ol = (z == 0) ? g_ql : (z == 1) ? g_kl : g_vl;
    gemm_body_pipe(A, Bth, Btl, oh, ol, nullptr, gsm,
                   blockIdx.x * 128, blockIdx.y * 64);
}

__global__ __launch_bounds__(256, 2) void gemm_out(float* __restrict__ out) {
    extern __shared__ char gsm[];
    gemm_body_pipe(g_O, g_wth + 3 * 32768, g_wtl + 3 * 32768, nullptr, nullptr, out,
                   gsm, blockIdx.x * 128, blockIdx.y * 64);
}

// ---------------- V transpose: g_vh/g_vl -> g_vth/g_vtl ----------------
__global__ __launch_bounds__(256) void vtrans(void) {
    __shared__ uint32_t sh[64 * 17], sl[64 * 17];
    const int tid = threadIdx.x;
    const int tb = blockIdx.x;
    const int n = blockIdx.y, h = blockIdx.z;

    const uint32_t* Vh = g_vh + ((size_t)n * TLEN + tb * 64) * 128 + h * 16;
    const uint32_t* Vl = g_vl + ((size_t)n * TLEN + tb * 64) * 128 + h * 16;
#pragma unroll
    for (int t = 0; t < 4; t++) {
        int idx = tid + t * 256;
        int r = idx >> 4, c = idx & 15;
        sh[r * 17 + c] = Vh[(size_t)r * 128 + c];
        sl[r * 17 + c] = Vl[(size_t)r * 128 + c];
    }
    __syncthreads();

    const uint16_t* sh16 = (const uint16_t*)sh;
    const uint16_t* sl16 = (const uint16_t*)sl;
    const int kp = tid & 31;
    const int dv0 = (tid >> 5) * 4;
    uint32_t* outh = g_vth + (((size_t)n * NH + h) * 32) * 1024 + tb * 32 + kp;
    uint32_t* outl = g_vtl + (((size_t)n * NH + h) * 32) * 1024 + tb * 32 + kp;
#pragma unroll
    for (int j = 0; j < 4; j++) {
        const int dv = dv0 + j;
        uint32_t a = sh16[(2 * kp) * 34 + dv];
        uint32_t b = sh16[(2 * kp + 1) * 34 + dv];
        outh[(size_t)dv * 1024] = a | (b << 16);
        uint32_t c = sl16[(2 * kp) * 34 + dv];
        uint32_t d = sl16[(2 * kp + 1) * 34 + dv];
        outl[(size_t)dv * 1024] = c | (d << 16);
    }
}

// ---------------- fused attention: R13 + swizzled smem relay for coalesced score STG ----
#define QS 20    // K/Q row stride in u32 (80 B)
#define VS 36    // V^T row stride in u32 (144 B)
#define OFF_QH    0          // 128 rows * 80 B = 10240
#define OFF_QL    10240
#define OFF_K     20480      // 3 bufs x 10240 = 30720
#define OFF_VT    51200      // 3 bufs x 9216 = 27648
#define OFF_RELAY 78848      // 128 rows x 256 B = 32768 (warp-private 8KB slices)
#define ATTN_SMEM 111616

__global__ void __launch_bounds__(128, 2) attn_mma(float* __restrict__ scores) {
    extern __shared__ char smem[];
    const uint32_t sb = smem_u32(smem);
    uint32_t* sQh = (uint32_t*)(smem + OFF_QH);
    uint32_t* sQl = (uint32_t*)(smem + OFF_QL);
    char* rel = smem + OFF_RELAY;

    const int tid = threadIdx.x;
    const int lane = tid & 31;
    const int wid = tid >> 5;      // 0..3
    const int qr = lane >> 2;
    const int lm = lane & 3;
    const int m0w = wid * 32;      // warp owns 32 q-rows

    const int qb = blockIdx.x, n = blockIdx.y, h = blockIdx.z;

    const uint32_t* Qh = g_qh + ((size_t)(n * TLEN + qb * 128)) * 128 + h * 16;
    const uint32_t* Ql = g_ql + ((size_t)(n * TLEN + qb * 128)) * 128 + h * 16;
    const uint32_t* Kh = g_kh + ((size_t)n * TLEN) * 128 + h * 16;
    const uint32_t* Kl = g_kl + ((size_t)n * TLEN) * 128 + h * 16;
    const uint32_t* Vth = g_vth + (((size_t)n * NH + h) * 32) * 1024;
    const uint32_t* Vtl = g_vtl + (((size_t)n * NH + h) * 32) * 1024;

    // ldmatrix lane offsets
    const uint32_t lko = (uint32_t)(lane & 7) * 80 + (uint32_t)(lane >> 3) * 16;
    const uint32_t lvo = ((uint32_t)((lane >> 4) * 8 + (lane & 7))) * 144
                       + (uint32_t)((lane >> 3) & 1) * 16;

    // staging (128 threads)
    auto issueKh128 = [&](int kb, uint32_t bufbase) {
#pragma unroll
        for (int t = 0; t < 4; t++) {
            int idx = tid + t * 128;
            int row = idx >> 2, col = (idx & 3) * 4;
            cp16(bufbase + (row * QS + col) * 4, Kh + (size_t)(kb + row) * 128 + col);
        }
    };
    auto issueKhl = [&](int kb, uint32_t bufbase) {
#pragma unroll
        for (int t = 0; t < 2; t++) {
            int idx = tid + t * 128;
            int row = idx >> 2, col = (idx & 3) * 4;
            cp16(bufbase + (row * QS + col) * 4,        Kh + (size_t)(kb + row) * 128 + col);
            cp16(bufbase + 5120 + (row * QS + col) * 4, Kl + (size_t)(kb + row) * 128 + col);
        }
    };
    auto issueVT = [&](int tile, uint32_t bufbase) {
#pragma unroll
        for (int t = 0; t < 2; t++) {
            int idx = tid + t * 128;
            int vr = idx >> 3, vc = (idx & 7) * 4;
            cp16(bufbase + (vr * VS + vc) * 4,        Vth + (size_t)vr * 1024 + tile * 32 + vc);
            cp16(bufbase + 4608 + (vr * VS + vc) * 4, Vtl + (size_t)vr * 1024 + tile * 32 + vc);
        }
    };

    // ---- stage Q once
#pragma unroll
    for (int t = 0; t < 16; t++) {
        int idx = tid + t * 128;
        int r = idx >> 4, c = idx & 15;
        sQh[r * QS + c] = Qh[(size_t)r * 128 + c];
        sQl[r * QS + c] = Ql[(size_t)r * 128 + c];
    }
    // prologue loop A: prefetch tiles 0 and 1 (3-stage, distance 2)
    issueKh128(0, sb + OFF_K);
    CP_COMMIT;
    issueKh128(128, sb + OFF_K + 10240);
    CP_COMMIT;
    __syncthreads();

    // ---- resident Q fragments: [mh][j][4]
    uint32_t aQh[2][2][4], aQl[2][2][4];
#pragma unroll
    for (int mh = 0; mh < 2; mh++)
#pragma unroll
        for (int j = 0; j < 2; j++) {
            uint32_t b0 = (m0w + mh * 16 + qr) * QS + j * 8 + lm;
            uint32_t b1 = b0 + 8 * QS;
            aQh[mh][j][0] = sQh[b0];     aQh[mh][j][1] = sQh[b1];
            aQh[mh][j][2] = sQh[b0 + 4]; aQh[mh][j][3] = sQh[b1 + 4];
            aQl[mh][j][0] = sQl[b0];     aQl[mh][j][1] = sQl[b1];
            aQl[mh][j][2] = sQl[b0 + 4]; aQl[mh][j][3] = sQl[b1 + 4];
        }

    float rs[2][2] = {{0.f, 0.f}, {0.f, 0.f}};

    // ================= Loop A: rowsums (hi-only QK, 128-key tiles, 3-stage) ==========
    {
        int cur = 0, nxt = 2;
        for (int tile = 0; tile < 16; tile++) {
            if (tile + 2 < 16) { CP_WAIT1; } else { CP_WAIT0; }
            __syncthreads();
            if (tile + 2 < 16) {
                issueKh128((tile + 2) * 128, sb + OFF_K + nxt * 10240);
                CP_COMMIT;
            }
            const uint32_t kbase = sb + OFF_K + cur * 10240 + lko;
            cur = (cur == 2) ? 0 : cur + 1;
            nxt = (nxt == 2) ? 0 : nxt + 1;

#pragma unroll
            for (int half = 0; half < 2; half++) {
#pragma unroll
                for (int f = 0; f < 8; f++) {
                    uint32_t h0, h1, h2, h3;
                    ldsm4(kbase + half * 5120 + f * 640, h0, h1, h2, h3);
#pragma unroll
                    for (int mh = 0; mh < 2; mh++) {
                        float S[4] = {0.f, 0.f, 0.f, 0.f};
                        mma_bf16(S, aQh[mh][0], h0, h1);
                        mma_bf16(S, aQh[mh][1], h2, h3);
                        rs[mh][0] += fast_exp2(S[0]) + fast_exp2(S[1]);
                        rs[mh][1] += fast_exp2(S[2]) + fast_exp2(S[3]);
                    }
                }
            }
        }
    }

    float li[2][2];
#pragma unroll
    for (int mh = 0; mh < 2; mh++)
#pragma unroll
        for (int r = 0; r < 2; r++) {
            float v = rs[mh][r];
            v += __shfl_xor_sync(0xFFFFFFFFu, v, 1);
            v += __shfl_xor_sync(0xFFFFFFFFu, v, 2);
            li[mh][r] = -__log2f(v);
        }

    // ================= Loop B: normalized scores + PV (3-stage, relay STG) ==========
    float O[2][4][4];
#pragma unroll
    for (int mh = 0; mh < 2; mh++)
#pragma unroll
        for (int g = 0; g < 4; g++)
#pragma unroll
            for (int i = 0; i < 4; i++) O[mh][g][i] = 0.0f;

    float* sbase = scores + ((size_t)((h * NB + n) * TLEN + qb * 128)) * TLEN;

    __syncthreads();   // loop A reads fully done before restaging
    issueKhl(0, sb + OFF_K);
    issueVT(0, sb + OFF_VT);
    CP_COMMIT;
    issueKhl(64, sb + OFF_K + 10240);
    issueVT(1, sb + OFF_VT + 9216);
    CP_COMMIT;

    {
        int cur = 0, nxt = 2;
        for (int tile = 0; tile < 32; tile++) {
            const int kb = tile * 64;
            if (tile + 2 < 32) { CP_WAIT1; } else { CP_WAIT0; }
            __syncthreads();
            if (tile + 2 < 32) {
                issueKhl((tile + 2) * 64, sb + OFF_K + nxt * 10240);
                issueVT(tile + 2, sb + OFF_VT + nxt * 9216);
                CP_COMMIT;
            }
            const uint32_t khb = sb + OFF_K + cur * 10240 + lko;
            const uint32_t klb = khb + 5120;
            const uint32_t vhb = sb + OFF_VT + cur * 9216 + lvo;
            const uint32_t vlb = vhb + 4608;
            cur = (cur == 2) ? 0 : cur + 1;
            nxt = (nxt == 2) ? 0 : nxt + 1;

            // ---- QK^T: 3-term split; K frags shared across both m-halves
            float S[2][8][4];
#pragma unroll
            for (int f = 0; f < 8; f++) {
                uint32_t h0, h1, h2, h3, l0, l1, l2, l3;
                ldsm4(khb + f * 640, h0, h1, h2, h3);
                ldsm4(klb + f * 640, l0, l1, l2, l3);
#pragma unroll
                for (int mh = 0; mh < 2; mh++) {
#pragma unroll
                    for (int i = 0; i < 4; i++) S[mh][f][i] = 0.0f;
                    mma_bf16(S[mh][f], aQh[mh][0], h0, h1);
                    mma_bf16(S[mh][f], aQh[mh][0], l0, l1);
                    mma_bf16(S[mh][f], aQl[mh][0], h0, h1);
                    mma_bf16(S[mh][f], aQh[mh][1], h2, h3);
                    mma_bf16(S[mh][f], aQh[mh][1], l2, l3);
                    mma_bf16(S[mh][f], aQl[mh][1], h2, h3);
                }
            }

            // ---- normalized exp + swizzled STS to warp-private relay
            // logical: relay row r (CTA-local), 256B/row; 16B unit j swizzled by j^((r&7)*2)
            {
                const int jj = 2 * 0;  // placeholder to keep scopes clear
                (void)jj;
#pragma unroll
                for (int mh = 0; mh < 2; mh++) {
                    const int r0 = m0w + mh * 16 + qr;   // rows r0 (vals 0,1) and r0+8 (vals 2,3)
                    const int sw = (r0 & 7) * 2;         // same for r0 and r0+8
#pragma unroll
                    for (int f = 0; f < 8; f++) {
                        float p0 = fast_exp2(S[mh][f][0] + li[mh][0]);
                        float p1 = fast_exp2(S[mh][f][1] + li[mh][0]);
                        float p2 = fast_exp2(S[mh][f][2] + li[mh][1]);
                        float p3 = fast_exp2(S[mh][f][3] + li[mh][1]);
                        S[mh][f][0] = p0; S[mh][f][1] = p1;
                        S[mh][f][2] = p2; S[mh][f][3] = p3;
                        const int unit = (f * 2 + (lm >> 1)) ^ sw;
                        const int off = r0 * 256 + unit * 16 + (lm & 1) * 8;
                        *(float2*)(rel + off)            = make_float2(p0, p1);
                        *(float2*)(rel + off + 8 * 256)  = make_float2(p2, p3);
                    }
                }
            }
            __syncwarp();

            // ---- coalesced score STG: warp reads its own relay rows, 128B lines
            {
                const int lrow = lane >> 3;      // 0..3
                const int u = lane & 7;          // 16B unit within half-row
#pragma unroll
                for (int g = 0; g < 8; g++) {
                    const int row = m0w + g * 4 + lrow;
                    float* gp = sbase + (size_t)row * TLEN + kb;
                    const int sw = (row & 7) * 2;
#pragma unroll
                    for (int half = 0; half < 2; half++) {
                        const int jl = u + half * 8;
                        const int up = jl ^ sw;
                        float4 v = *(const float4*)(rel + row * 256 + up * 16);
                        __stcs((float4*)(gp + jl * 4), v);
                    }
                }
            }

            // ---- PV: 3-term split; V frags shared across both m-halves
#pragma unroll
            for (int kk = 0; kk < 4; kk++) {
                uint32_t vh0, vh1, vh2, vh3, vh4, vh5, vh6, vh7;
                uint32_t vl0, vl1, vl2, vl3, vl4, vl5, vl6, vl7;
                ldsm4(vhb + kk * 32,        vh0, vh1, vh2, vh3);
                ldsm4(vhb + 2304 + kk * 32, vh4, vh5, vh6, vh7);
                ldsm4(vlb + kk * 32,        vl0, vl1, vl2, vl3);
                ldsm4(vlb + 2304 + kk * 32, vl4, vl5, vl6, vl7);

#pragma unroll
                for (int mh = 0; mh < 2; mh++) {
                    uint32_t ah[4], al[4];
                    split2(S[mh][2 * kk][0],     S[mh][2 * kk][1],     ah[0], al[0]);
                    split2(S[mh][2 * kk][2],     S[mh][2 * kk][3],     ah[1], al[1]);
                    split2(S[mh][2 * kk + 1][0], S[mh][2 * kk + 1][1], ah[2], al[2]);
                    split2(S[mh][2 * kk + 1][2], S[mh][2 * kk + 1][3], ah[3], al[3]);

                    mma_bf16(O[mh][0], ah, vh0, vh1);
                    mma_bf16(O[mh][0], ah, vl0, vl1);
                    mma_bf16(O[mh][0], al, vh0, vh1);
                    mma_bf16(O[mh][1], ah, vh2, vh3);
                    mma_bf16(O[mh][1], ah, vl2, vl3);
                    mma_bf16(O[mh][1], al, vh2, vh3);
                    mma_bf16(O[mh][2], ah, vh4, vh5);
                    mma_bf16(O[mh][2], ah, vl4, vl5);
                    mma_bf16(O[mh][2], al, vh4, vh5);
                    mma_bf16(O[mh][3], ah, vh6, vh7);
                    mma_bf16(O[mh][3], ah, vl6, vl7);
                    mma_bf16(O[mh][3], al, vh6, vh7);
                }
            }
        }
    }

    // ---- O write (already normalized): [n, T, h*32 + dv]
#pragma unroll
    for (int mh = 0; mh < 2; mh++) {
        float* Og0 = g_O + ((size_t)(n * TLEN + qb * 128 + m0w + mh * 16 + qr)) * DM + h * DK;
        float* Og1 = Og0 + 8 * (size_t)DM;
#pragma unroll
        for (int g = 0; g < 4; g++) {
            const int col = g * 8 + lm * 2;
            *(float2*)(Og0 + col) = make_float2(O[mh][g][0], O[mh][g][1]);
            *(float2*)(Og1 + col) = make_float2(O[mh][g][2], O[mh][g][3]);
        }
    }
}

// ---------------- launcher ----------------
extern "C" void kernel_launch(void* const* d_in, const int* in_sizes, int n_in,
                              void* d_out, int out_size) {
    (void)in_sizes; (void)n_in; (void)out_size;
    const float* query = (const float*)d_in[0];
    const float* key   = (const float*)d_in[1];
    const float* Wq    = (const float*)d_in[2];
    const float* Wk    = (const float*)d_in[3];
    const float* Wv    = (const float*)d_in[4];
    const float* Wo    = (const float*)d_in[5];

    float* out    = (float*)d_out;                      // [4, 2048, 256]
    float* scores = (float*)d_out + (size_t)ROWS * DM;  // [8, 4, 2048, 2048]

    static bool attr_set = false;
    if (!attr_set) {
        cudaFuncSetAttribute(attn_mma, cudaFuncAttributeMaxDynamicSharedMemorySize,
                             ATTN_SMEM);
        cudaFuncSetAttribute(gemm3, cudaFuncAttributeMaxDynamicSharedMemorySize,
                             GEMM_SMEM);
        cudaFuncSetAttribute(gemm_out, cudaFuncAttributeMaxDynamicSharedMemorySize,
                             GEMM_SMEM);
        attr_set = true;
    }

    prep_w<<<512, 256>>>(Wq, Wk, Wv, Wo);

    dim3 g3(ROWS / 128, DM / 64, 3);   // (64, 4, 3) merged Q/K/V projections
    gemm3<<<g3, 256, GEMM_SMEM>>>(query, key);

    dim3 vg(TLEN / 64, NB, NH);        // (32, 4, 8)
    vtrans<<<vg, 256>>>();

    dim3 attnGrid(TLEN / 128, NB, NH); // (16, 4, 8) = 512 CTAs, 128 q-rows each
    attn_mma<<<attnGrid, 128, ATTN_SMEM>>>(scores);

    dim3 gg(ROWS / 128, DM / 64);      // (64, 4)
    gemm_out<<<gg, 256, GEMM_SMEM>>>(out);
}

// round 15
// speedup vs baseline: 1.0929x; 1.0929x over previous
#include <cuda_runtime.h>
#include <cuda_bf16.h>
#include <cstdint>

// Problem constants
#define NH   8
#define DK   32
#define TLEN 2048
#define NB   4
#define DM   256
#define ROWS (NB * TLEN)   // 8192

// ---------------- device scratch (allocation-free rule) ----------------
__device__ uint32_t g_qh[ROWS * 128], g_ql[ROWS * 128];
__device__ uint32_t g_kh[ROWS * 128], g_kl[ROWS * 128];
__device__ float    g_O [ROWS * DM];
// transposed split weights: [4 W][256 n][128 kpair]
__device__ uint32_t g_wth[4 * 256 * 128], g_wtl[4 * 256 * 128];
// pre-transposed V: [n][h][32 dv][1024 keypair u32]
__device__ uint32_t g_vth[NB * NH * 32 * 1024], g_vtl[NB * NH * 32 * 1024];

// ---------------- helpers ----------------
__device__ __forceinline__ float fast_exp2(float x) {
    float y;
    asm("ex2.approx.f32 %0, %1;" : "=f"(y) : "f"(x));
    return y;
}
__device__ __forceinline__ uint32_t packbf2(float x0, float x1) {
    uint32_t d;
    asm("cvt.rn.bf16x2.f32 %0, %1, %2;" : "=r"(d) : "f"(x1), "f"(x0));
    return d;
}
__device__ __forceinline__ void split2(float x0, float x1, uint32_t& h, uint32_t& l) {
    h = packbf2(x0, x1);
    float h0 = __uint_as_float(h << 16);
    float h1 = __uint_as_float(h & 0xFFFF0000u);
    l = packbf2(x0 - h0, x1 - h1);
}
__device__ __forceinline__ void mma_bf16(float* c, const uint32_t* a,
                                         uint32_t b0, uint32_t b1) {
    asm volatile(
        "mma.sync.aligned.m16n8k16.row.col.f32.bf16.bf16.f32 "
        "{%0,%1,%2,%3}, {%4,%5,%6,%7}, {%8,%9}, {%0,%1,%2,%3};"
        : "+f"(c[0]), "+f"(c[1]), "+f"(c[2]), "+f"(c[3])
        : "r"(a[0]), "r"(a[1]), "r"(a[2]), "r"(a[3]), "r"(b0), "r"(b1));
}
__device__ __forceinline__ void mma_bf16r(float* c, uint32_t a0, uint32_t a1,
                                          uint32_t a2, uint32_t a3,
                                          uint32_t b0, uint32_t b1) {
    asm volatile(
        "mma.sync.aligned.m16n8k16.row.col.f32.bf16.bf16.f32 "
        "{%0,%1,%2,%3}, {%4,%5,%6,%7}, {%8,%9}, {%0,%1,%2,%3};"
        : "+f"(c[0]), "+f"(c[1]), "+f"(c[2]), "+f"(c[3])
        : "r"(a0), "r"(a1), "r"(a2), "r"(a3), "r"(b0), "r"(b1));
}
__device__ __forceinline__ void ldsm4(uint32_t addr, uint32_t& r0, uint32_t& r1,
                                      uint32_t& r2, uint32_t& r3) {
    asm volatile("ldmatrix.sync.aligned.m8n8.x4.shared.b16 {%0,%1,%2,%3}, [%4];"
                 : "=r"(r0), "=r"(r1), "=r"(r2), "=r"(r3) : "r"(addr));
}
__device__ __forceinline__ uint32_t smem_u32(const void* p) {
    uint32_t a;
    asm("{ .reg .u64 t; cvta.to.shared.u64 t, %1; cvt.u32.u64 %0, t; }" : "=r"(a) : "l"(p));
    return a;
}
__device__ __forceinline__ void cp16(uint32_t daddr, const void* g) {
    asm volatile("cp.async.ca.shared.global [%0], [%1], 16;"
                 :: "r"(daddr), "l"(g) : "memory");
}
#define CP_COMMIT asm volatile("cp.async.commit_group;" ::: "memory")
#define CP_WAIT0  asm volatile("cp.async.wait_group 0;" ::: "memory")
#define CP_WAIT1  asm volatile("cp.async.wait_group 1;" ::: "memory")

// ---------------- prep: W -> transposed split bf16 pairs (Wq pre-scaled) ----------------
__global__ __launch_bounds__(256) void prep_w(const float* __restrict__ W0,
                                              const float* __restrict__ W1,
                                              const float* __restrict__ W2,
                                              const float* __restrict__ W3) {
    const int idx = blockIdx.x * 256 + threadIdx.x;
    const int w = idx >> 15;
    const int r = idx & 32767;
    const int n = r >> 7, kp = r & 127;
    const float* W = (w == 0) ? W0 : (w == 1) ? W1 : (w == 2) ? W2 : W3;
    const float sc = (w == 0) ? 0.25503480f : 1.0f;   // log2(e)/sqrt(32) folded into Wq
    float x0 = W[(size_t)(2 * kp) * 256 + n] * sc;
    float x1 = W[(size_t)(2 * kp + 1) * 256 + n] * sc;
    uint32_t h, l;
    split2(x0, x1, h, l);
    g_wth[idx] = h;
    g_wtl[idx] = l;
}

// ---------------- software-pipelined HMMA GEMM: C = A @ W ----------------
// MODE 0: write split bf16 hi/lo pairs to outh/outl
// MODE 1: write f32 to outf
// MODE 2: V path — transposed split write directly to g_vth/g_vtl (fused vtrans)
#define GS 20
#define GB_AL 10240
#define GB_BH 20480
#define GB_BL 25600
#define GBUF  30720
#define GEMM_SMEM (2 * GBUF)

template <int MODE>
__device__ __forceinline__ void gemm_body_pipe(const float* __restrict__ A,
                                               const uint32_t* __restrict__ Bth,
                                               const uint32_t* __restrict__ Btl,
                                               uint32_t* __restrict__ outh,
                                               uint32_t* __restrict__ outl,
                                               float* __restrict__ outf,
                                               char* gsm, int bm, int bn) {
    const int tid = threadIdx.x;
    const int lane = tid & 31;
    const int wid = tid >> 5;
    const int qr = lane >> 2;
    const int lm = lane & 3;
    const int m0w = wid * 16;

    const int br = tid >> 2;
    const int bc = (tid & 3) * 4;

    float4 pa[4];
    uint4 pbh, pbl;

    auto ldg = [&](int kc) {
#pragma unroll
        for (int t = 0; t < 4; t++) {
            int idx = tid + t * 256;
            int r = idx >> 3, c4 = idx & 7;
            pa[t] = *(const float4*)&A[(size_t)(bm + r) * 256 + kc * 32 + c4 * 4];
        }
        pbh = *(const uint4*)&Bth[(size_t)(bn + br) * 128 + kc * 16 + bc];
        pbl = *(const uint4*)&Btl[(size_t)(bn + br) * 128 + kc * 16 + bc];
    };
    auto sts = [&](int buf) {
        uint32_t* sAh = (uint32_t*)(gsm + buf * GBUF);
        uint32_t* sAl = (uint32_t*)(gsm + buf * GBUF + GB_AL);
        uint32_t* sBh = (uint32_t*)(gsm + buf * GBUF + GB_BH);
        uint32_t* sBl = (uint32_t*)(gsm + buf * GBUF + GB_BL);
#pragma unroll
        for (int t = 0; t < 4; t++) {
            int idx = tid + t * 256;
            int r = idx >> 3, c4 = idx & 7;
            uint32_t h0, l0, h1, l1;
            split2(pa[t].x, pa[t].y, h0, l0);
            split2(pa[t].z, pa[t].w, h1, l1);
            sAh[r * GS + c4 * 2]     = h0;
            sAh[r * GS + c4 * 2 + 1] = h1;
            sAl[r * GS + c4 * 2]     = l0;
            sAl[r * GS + c4 * 2 + 1] = l1;
        }
        *(uint4*)&sBh[br * GS + bc] = pbh;
        *(uint4*)&sBl[br * GS + bc] = pbl;
    };

    float C[8][4];
#pragma unroll
    for (int f = 0; f < 8; f++)
#pragma unroll
        for (int i = 0; i < 4; i++) C[f][i] = 0.0f;

    ldg(0);
    sts(0);
    __syncthreads();

    for (int kc = 0; kc < 8; kc++) {
        const int cur = kc & 1;
        if (kc + 1 < 8) ldg(kc + 1);

        const uint32_t* sAh = (const uint32_t*)(gsm + cur * GBUF);
        const uint32_t* sAl = (const uint32_t*)(gsm + cur * GBUF + GB_AL);
        const uint32_t* sBh = (const uint32_t*)(gsm + cur * GBUF + GB_BH);
        const uint32_t* sBl = (const uint32_t*)(gsm + cur * GBUF + GB_BL);

#pragma unroll
        for (int j = 0; j < 2; j++) {
            const int ab = (m0w + qr) * GS + j * 8 + lm;
            uint32_t ah0 = sAh[ab],     ah1 = sAh[ab + 8 * GS];
            uint32_t ah2 = sAh[ab + 4], ah3 = sAh[ab + 8 * GS + 4];
            uint32_t al0 = sAl[ab],     al1 = sAl[ab + 8 * GS];
            uint32_t al2 = sAl[ab + 4], al3 = sAl[ab + 8 * GS + 4];
#pragma unroll
            for (int f = 0; f < 8; f++) {
                const int bb = (f * 8 + qr) * GS + j * 8 + lm;
                uint32_t bh0 = sBh[bb], bh1 = sBh[bb + 4];
                uint32_t bl0 = sBl[bb], bl1 = sBl[bb + 4];
                mma_bf16r(C[f], ah0, ah1, ah2, ah3, bh0, bh1);
                mma_bf16r(C[f], ah0, ah1, ah2, ah3, bl0, bl1);
                mma_bf16r(C[f], al0, al1, al2, al3, bh0, bh1);
            }
        }
        if (kc + 1 < 8) sts(cur ^ 1);
        __syncthreads();
    }

    if (MODE == 0) {
#pragma unroll
        for (int f = 0; f < 8; f++) {
            uint32_t h, l;
            size_t o0 = (size_t)(bm + m0w + qr) * 128 + (bn >> 1) + f * 4 + lm;
            split2(C[f][0], C[f][1], h, l);
            outh[o0] = h; outl[o0] = l;
            split2(C[f][2], C[f][3], h, l);
            outh[o0 + 8 * 128] = h; outl[o0 + 8 * 128] = l;
        }
    } else if (MODE == 1) {
#pragma unroll
        for (int f = 0; f < 8; f++) {
            size_t r0 = (size_t)(bm + m0w + qr) * 256 + bn + f * 8 + lm * 2;
            *(float2*)&outf[r0]           = make_float2(C[f][0], C[f][1]);
            *(float2*)&outf[r0 + 8 * 256] = make_float2(C[f][2], C[f][3]);
        }
    } else {
        // MODE 2: fused V transpose. Stage split C into smem [128 rows][33 u32],
        // then write g_vth/g_vtl transposed & coalesced.
        uint32_t* svh32 = (uint32_t*)gsm;              // 128*33*4 = 16896 B
        uint32_t* svl32 = (uint32_t*)(gsm + 16896);    // 16896 B (total 33792 <= 61440)
        const int lr0 = m0w + qr, lr1 = lr0 + 8;
#pragma unroll
        for (int f = 0; f < 8; f++) {
            uint32_t h, l;
            split2(C[f][0], C[f][1], h, l);
            svh32[lr0 * 33 + f * 4 + lm] = h;
            svl32[lr0 * 33 + f * 4 + lm] = l;
            split2(C[f][2], C[f][3], h, l);
            svh32[lr1 * 33 + f * 4 + lm] = h;
            svl32[lr1 * 33 + f * 4 + lm] = l;
        }
        __syncthreads();
        const uint16_t* svh16 = (const uint16_t*)svh32;
        const uint16_t* svl16 = (const uint16_t*)svl32;
        const int kpl = tid & 63;                 // keypair within tile (0..63)
        const int colbase = (tid >> 6) * 16;      // 4 groups x 16 cols
        const int nn = bm / TLEN;
        const int kpg = (bm % TLEN) / 2 + kpl;
#pragma unroll
        for (int j = 0; j < 16; j++) {
            const int col = colbase + j;          // 0..63
            const int gc = bn + col;              // global dm col
            const int hh = gc >> 5, dv = gc & 31;
            const size_t ob = (((size_t)nn * NH + hh) * 32 + dv) * 1024 + kpg;
            uint32_t a = svh16[(2 * kpl) * 66 + col];
            uint32_t b = svh16[(2 * kpl + 1) * 66 + col];
            g_vth[ob] = a | (b << 16);
            uint32_t c = svl16[(2 * kpl) * 66 + col];
            uint32_t d = svl16[(2 * kpl + 1) * 66 + col];
            g_vtl[ob] = c | (d << 16);
        }
    }
}

// merged Q/K/V projection: z=0 query->Q (SC-scaled), z=1 query->K, z=2 key->V(transposed)
__global__ __launch_bounds__(256, 2) void gemm3(const float* __restrict__ query,
                                                const float* __restrict__ key) {
    extern __shared__ char gsm[];
    const int z = blockIdx.z;
    if (z == 0) {
        gemm_body_pipe<0>(query, g_wth, g_wtl, g_qh, g_ql, nullptr, gsm,
                          blockIdx.x * 128, blockIdx.y * 64);
    } else if (z == 1) {
        gemm_body_pipe<0>(query, g_wth + 32768, g_wtl + 32768, g_kh, g_kl, nullptr, gsm,
                          blockIdx.x * 128, blockIdx.y * 64);
    } else {
        gemm_body_pipe<2>(key, g_wth + 2 * 32768, g_wtl + 2 * 32768, nullptr, nullptr,
                          nullptr, gsm, blockIdx.x * 128, blockIdx.y * 64);
    }
}

__global__ __launch_bounds__(256, 2) void gemm_out(float* __restrict__ out) {
    extern __shared__ char gsm[];
    gemm_body_pipe<1>(g_O, g_wth + 3 * 32768, g_wtl + 3 * 32768, nullptr, nullptr, out,
                      gsm, blockIdx.x * 128, blockIdx.y * 64);
}

// ---------------- fused attention: R13 (3-stage cp.async, M=32/warp, 2 CTA/SM) ----------
#define QS 20    // K/Q row stride in u32 (80 B)
#define VS 36    // V^T row stride in u32 (144 B)
#define OFF_QH   0          // 128 rows * 80 B = 10240
#define OFF_QL   10240
#define OFF_K    20480      // 3 bufs x 10240 = 30720
#define OFF_VT   51200      // 3 bufs x 9216 = 27648
#define ATTN_SMEM 78848

__global__ void __launch_bounds__(128, 2) attn_mma(float* __restrict__ scores) {
    extern __shared__ char smem[];
    const uint32_t sb = smem_u32(smem);
    uint32_t* sQh = (uint32_t*)(smem + OFF_QH);
    uint32_t* sQl = (uint32_t*)(smem + OFF_QL);

    const int tid = threadIdx.x;
    const int lane = tid & 31;
    const int wid = tid >> 5;      // 0..3
    const int qr = lane >> 2;
    const int lm = lane & 3;
    const int m0w = wid * 32;      // warp owns 32 q-rows

    const int qb = blockIdx.x, n = blockIdx.y, h = blockIdx.z;

    const uint32_t* Qh = g_qh + ((size_t)(n * TLEN + qb * 128)) * 128 + h * 16;
    const uint32_t* Ql = g_ql + ((size_t)(n * TLEN + qb * 128)) * 128 + h * 16;
    const uint32_t* Kh = g_kh + ((size_t)n * TLEN) * 128 + h * 16;
    const uint32_t* Kl = g_kl + ((size_t)n * TLEN) * 128 + h * 16;
    const uint32_t* Vth = g_vth + (((size_t)n * NH + h) * 32) * 1024;
    const uint32_t* Vtl = g_vtl + (((size_t)n * NH + h) * 32) * 1024;

    // ldmatrix lane offsets
    const uint32_t lko = (uint32_t)(lane & 7) * 80 + (uint32_t)(lane >> 3) * 16;
    const uint32_t lvo = ((uint32_t)((lane >> 4) * 8 + (lane & 7))) * 144
                       + (uint32_t)((lane >> 3) & 1) * 16;

    // staging (128 threads)
    auto issueKh128 = [&](int kb, uint32_t bufbase) {
#pragma unroll
        for (int t = 0; t < 4; t++) {
            int idx = tid + t * 128;
            int row = idx >> 2, col = (idx & 3) * 4;
            cp16(bufbase + (row * QS + col) * 4, Kh + (size_t)(kb + row) * 128 + col);
        }
    };
    auto issueKhl = [&](int kb, uint32_t bufbase) {
#pragma unroll
        for (int t = 0; t < 2; t++) {
            int idx = tid + t * 128;
            int row = idx >> 2, col = (idx & 3) * 4;
            cp16(bufbase + (row * QS + col) * 4,        Kh + (size_t)(kb + row) * 128 + col);
            cp16(bufbase + 5120 + (row * QS + col) * 4, Kl + (size_t)(kb + row) * 128 + col);
        }
    };
    auto issueVT = [&](int tile, uint32_t bufbase) {
#pragma unroll
        for (int t = 0; t < 2; t++) {
            int idx = tid + t * 128;
            int vr = idx >> 3, vc = (idx & 7) * 4;
            cp16(bufbase + (vr * VS + vc) * 4,        Vth + (size_t)vr * 1024 + tile * 32 + vc);
            cp16(bufbase + 4608 + (vr * VS + vc) * 4, Vtl + (size_t)vr * 1024 + tile * 32 + vc);
        }
    };

    // ---- stage Q once
#pragma unroll
    for (int t = 0; t < 16; t++) {
        int idx = tid + t * 128;
        int r = idx >> 4, c = idx & 15;
        sQh[r * QS + c] = Qh[(size_t)r * 128 + c];
        sQl[r * QS + c] = Ql[(size_t)r * 128 + c];
    }
    // prologue loop A: prefetch tiles 0 and 1 (3-stage, distance 2)
    issueKh128(0, sb + OFF_K);
    CP_COMMIT;
    issueKh128(128, sb + OFF_K + 10240);
    CP_COMMIT;
    __syncthreads();

    // ---- resident Q fragments: [mh][j][4]
    uint32_t aQh[2][2][4], aQl[2][2][4];
#pragma unroll
    for (int mh = 0; mh < 2; mh++)
#pragma unroll
        for (int j = 0; j < 2; j++) {
            uint32_t b0 = (m0w + mh * 16 + qr) * QS + j * 8 + lm;
            uint32_t b1 = b0 + 8 * QS;
            aQh[mh][j][0] = sQh[b0];     aQh[mh][j][1] = sQh[b1];
            aQh[mh][j][2] = sQh[b0 + 4]; aQh[mh][j][3] = sQh[b1 + 4];
            aQl[mh][j][0] = sQl[b0];     aQl[mh][j][1] = sQl[b1];
            aQl[mh][j][2] = sQl[b0 + 4]; aQl[mh][j][3] = sQl[b1 + 4];
        }

    float rs[2][2] = {{0.f, 0.f}, {0.f, 0.f}};

    // ================= Loop A: rowsums (hi-only QK, 128-key tiles, 3-stage) ==========
    {
        int cur = 0, nxt = 2;
        for (int tile = 0; tile < 16; tile++) {
            if (tile + 2 < 16) { CP_WAIT1; } else { CP_WAIT0; }
            __syncthreads();
            if (tile + 2 < 16) {
                issueKh128((tile + 2) * 128, sb + OFF_K + nxt * 10240);
                CP_COMMIT;
            }
            const uint32_t kbase = sb + OFF_K + cur * 10240 + lko;
            cur = (cur == 2) ? 0 : cur + 1;
            nxt = (nxt == 2) ? 0 : nxt + 1;

#pragma unroll
            for (int half = 0; half < 2; half++) {
#pragma unroll
                for (int f = 0; f < 8; f++) {
                    uint32_t h0, h1, h2, h3;
                    ldsm4(kbase + half * 5120 + f * 640, h0, h1, h2, h3);
#pragma unroll
                    for (int mh = 0; mh < 2; mh++) {
                        float S[4] = {0.f, 0.f, 0.f, 0.f};
                        mma_bf16(S, aQh[mh][0], h0, h1);
                        mma_bf16(S, aQh[mh][1], h2, h3);
                        rs[mh][0] += fast_exp2(S[0]) + fast_exp2(S[1]);
                        rs[mh][1] += fast_exp2(S[2]) + fast_exp2(S[3]);
                    }
                }
            }
        }
    }

    float li[2][2];
#pragma unroll
    for (int mh = 0; mh < 2; mh++)
#pragma unroll
        for (int r = 0; r < 2; r++) {
            float v = rs[mh][r];
            v += __shfl_xor_sync(0xFFFFFFFFu, v, 1);
            v += __shfl_xor_sync(0xFFFFFFFFu, v, 2);
            li[mh][r] = -__log2f(v);
        }

    // ================= Loop B: normalized scores + PV (3-stage) =================
    float O[2][4][4];
#pragma unroll
    for (int mh = 0; mh < 2; mh++)
#pragma unroll
        for (int g = 0; g < 4; g++)
#pragma unroll
            for (int i = 0; i < 4; i++) O[mh][g][i] = 0.0f;

    float* srow[2][2];
#pragma unroll
    for (int mh = 0; mh < 2; mh++) {
        srow[mh][0] = scores + ((size_t)((h * NB + n) * TLEN + qb * 128 + m0w + mh * 16 + qr)) * TLEN;
        srow[mh][1] = srow[mh][0] + 8 * (size_t)TLEN;
    }

    __syncthreads();   // loop A reads fully done before restaging
    issueKhl(0, sb + OFF_K);
    issueVT(0, sb + OFF_VT);
    CP_COMMIT;
    issueKhl(64, sb + OFF_K + 10240);
    issueVT(1, sb + OFF_VT + 9216);
    CP_COMMIT;

    {
        int cur = 0, nxt = 2;
        for (int tile = 0; tile < 32; tile++) {
            const int kb = tile * 64;
            if (tile + 2 < 32) { CP_WAIT1; } else { CP_WAIT0; }
            __syncthreads();
            if (tile + 2 < 32) {
                issueKhl((tile + 2) * 64, sb + OFF_K + nxt * 10240);
                issueVT(tile + 2, sb + OFF_VT + nxt * 9216);
                CP_COMMIT;
            }
            const uint32_t khb = sb + OFF_K + cur * 10240 + lko;
            const uint32_t klb = khb + 5120;
            const uint32_t vhb = sb + OFF_VT + cur * 9216 + lvo;
            const uint32_t vlb = vhb + 4608;
            cur = (cur == 2) ? 0 : cur + 1;
            nxt = (nxt == 2) ? 0 : nxt + 1;

            // ---- QK^T: 3-term split; K frags shared across both m-halves
            float S[2][8][4];
#pragma unroll
            for (int f = 0; f < 8; f++) {
                uint32_t h0, h1, h2, h3, l0, l1, l2, l3;
                ldsm4(khb + f * 640, h0, h1, h2, h3);
                ldsm4(klb + f * 640, l0, l1, l2, l3);
#pragma unroll
                for (int mh = 0; mh < 2; mh++) {
#pragma unroll
                    for (int i = 0; i < 4; i++) S[mh][f][i] = 0.0f;
                    mma_bf16(S[mh][f], aQh[mh][0], h0, h1);
                    mma_bf16(S[mh][f], aQh[mh][0], l0, l1);
                    mma_bf16(S[mh][f], aQl[mh][0], h0, h1);
                    mma_bf16(S[mh][f], aQh[mh][1], h2, h3);
                    mma_bf16(S[mh][f], aQh[mh][1], l2, l3);
                    mma_bf16(S[mh][f], aQl[mh][1], h2, h3);
                }
            }

            // ---- normalized exp + final score store
#pragma unroll
            for (int mh = 0; mh < 2; mh++)
#pragma unroll
                for (int f = 0; f < 8; f++) {
                    float p0 = fast_exp2(S[mh][f][0] + li[mh][0]);
                    float p1 = fast_exp2(S[mh][f][1] + li[mh][0]);
                    float p2 = fast_exp2(S[mh][f][2] + li[mh][1]);
                    float p3 = fast_exp2(S[mh][f][3] + li[mh][1]);
                    S[mh][f][0] = p0; S[mh][f][1] = p1;
                    S[mh][f][2] = p2; S[mh][f][3] = p3;
                    const int col = kb + f * 8 + lm * 2;
                    __stcs((float2*)(srow[mh][0] + col), make_float2(p0, p1));
                    __stcs((float2*)(srow[mh][1] + col), make_float2(p2, p3));
                }

            // ---- PV: 3-term split; V frags shared across both m-halves
#pragma unroll
            for (int kk = 0; kk < 4; kk++) {
                uint32_t vh0, vh1, vh2, vh3, vh4, vh5, vh6, vh7;
                uint32_t vl0, vl1, vl2, vl3, vl4, vl5, vl6, vl7;
                ldsm4(vhb + kk * 32,        vh0, vh1, vh2, vh3);
                ldsm4(vhb + 2304 + kk * 32, vh4, vh5, vh6, vh7);
                ldsm4(vlb + kk * 32,        vl0, vl1, vl2, vl3);
                ldsm4(vlb + 2304 + kk * 32, vl4, vl5, vl6, vl7);

#pragma unroll
                for (int mh = 0; mh < 2; mh++) {
                    uint32_t ah[4], al[4];
                    split2(S[mh][2 * kk][0],     S[mh][2 * kk][1],     ah[0], al[0]);
                    split2(S[mh][2 * kk][2],     S[mh][2 * kk][3],     ah[1], al[1]);
                    split2(S[mh][2 * kk + 1][0], S[mh][2 * kk + 1][1], ah[2], al[2]);
                    split2(S[mh][2 * kk + 1][2], S[mh][2 * kk + 1][3], ah[3], al[3]);

                    mma_bf16(O[mh][0], ah, vh0, vh1);
                    mma_bf16(O[mh][0], ah, vl0, vl1);
                    mma_bf16(O[mh][0], al, vh0, vh1);
                    mma_bf16(O[mh][1], ah, vh2, vh3);
                    mma_bf16(O[mh][1], ah, vl2, vl3);
                    mma_bf16(O[mh][1], al, vh2, vh3);
                    mma_bf16(O[mh][2], ah, vh4, vh5);
                    mma_bf16(O[mh][2], ah, vl4, vl5);
                    mma_bf16(O[mh][2], al, vh4, vh5);
                    mma_bf16(O[mh][3], ah, vh6, vh7);
                    mma_bf16(O[mh][3], ah, vl6, vl7);
                    mma_bf16(O[mh][3], al, vh6, vh7);
                }
            }
        }
    }

    // ---- O write (already normalized): [n, T, h*32 + dv]
#pragma unroll
    for (int mh = 0; mh < 2; mh++) {
        float* Og0 = g_O + ((size_t)(n * TLEN + qb * 128 + m0w + mh * 16 + qr)) * DM + h * DK;
        float* Og1 = Og0 + 8 * (size_t)DM;
#pragma unroll
        for (int g = 0; g < 4; g++) {
            const int col = g * 8 + lm * 2;
            *(float2*)(Og0 + col) = make_float2(O[mh][g][0], O[mh][g][1]);
            *(float2*)(Og1 + col) = make_float2(O[mh][g][2], O[mh][g][3]);
        }
    }
}

// ---------------- launcher ----------------
extern "C" void kernel_launch(void* const* d_in, const int* in_sizes, int n_in,
                              void* d_out, int out_size) {
    (void)in_sizes; (void)n_in; (void)out_size;
    const float* query = (const float*)d_in[0];
    const float* key   = (const float*)d_in[1];
    const float* Wq    = (const float*)d_in[2];
    const float* Wk    = (const float*)d_in[3];
    const float* Wv    = (const float*)d_in[4];
    const float* Wo    = (const float*)d_in[5];

    float* out    = (float*)d_out;                      // [4, 2048, 256]
    float* scores = (float*)d_out + (size_t)ROWS * DM;  // [8, 4, 2048, 2048]

    static bool attr_set = false;
    if (!attr_set) {
        cudaFuncSetAttribute(attn_mma, cudaFuncAttributeMaxDynamicSharedMemorySize,
                             ATTN_SMEM);
        cudaFuncSetAttribute(gemm3, cudaFuncAttributeMaxDynamicSharedMemorySize,
                             GEMM_SMEM);
        cudaFuncSetAttribute(gemm_out, cudaFuncAttributeMaxDynamicSharedMemorySize,
                             GEMM_SMEM);
        attr_set = true;
    }

    prep_w<<<512, 256>>>(Wq, Wk, Wv, Wo);

    dim3 g3(ROWS / 128, DM / 64, 3);   // (64, 4, 3) merged Q/K/V projections (V transposed)
    gemm3<<<g3, 256, GEMM_SMEM>>>(query, key);

    dim3 attnGrid(TLEN / 128, NB, NH); // (16, 4, 8) = 512 CTAs, 128 q-rows each
    attn_mma<<<attnGrid, 128, ATTN_SMEM>>>(scores);

    dim3 gg(ROWS / 128, DM / 64);      // (64, 4)
    gemm_out<<<gg, 256, GEMM_SMEM>>>(out);
}